// round 7
// baseline (speedup 1.0000x reference)
#include <cuda_runtime.h>
#include <cstdint>

// Shapes fixed: value [8,4096,1024], last [8,1024], W [1024,1024], b [1024].
#define BB 8
#define TT 4096
#define HH 1024

#define RANGES 32              // T-splits per batch (fused kernel grid.x)
#define TR (TT / RANGES)       // 128 timesteps per block
#define NW 8                   // warps per fused block (256 threads)
#define NITER (TR / NW)        // 16 iterations, 1 row per warp per iter

#define OCH 128                // o-splits for query partials
#define OSEG (HH / OCH)        // 8

// -------- scratch (__device__ globals; no allocation allowed) --------
__device__ __align__(16) float g_qpart[OCH * BB * HH]; // 4 MB (L2-resident)
__device__ __align__(16) float g_q[BB * HH];           // 32 KB reduced q
__device__ __align__(16) float g_cpart[BB * RANGES * HH]; // 1 MB
__device__ float g_mpart[BB * RANGES];
__device__ float g_spart[BB * RANGES];

// ---------------------------------------------------------------------
// Kernel 1: query partials. qpart[oc,b,h] = sum_{o in chunk oc} W[o,h]*last[b,o]
// grid (HH/128, OCH) = 1024 blocks, block 128. 8 fully-unrolled W loads per
// thread, 8 batches per W element. W (4 MB) streamed exactly once.
// ---------------------------------------------------------------------
__global__ void k_query_part(const float* __restrict__ W,
                             const float* __restrict__ last) {
    __shared__ float ls[BB * OSEG];   // 64 floats
    const int oc = blockIdx.y;
    const int h  = blockIdx.x * 128 + threadIdx.x;

    if (threadIdx.x < BB * OSEG) {
        int b = threadIdx.x / OSEG, o = threadIdx.x % OSEG;
        ls[threadIdx.x] = last[b * HH + oc * OSEG + o];
    }
    __syncthreads();

    float wv[OSEG];
#pragma unroll
    for (int o = 0; o < OSEG; o++)
        wv[o] = W[(size_t)(oc * OSEG + o) * HH + h];

    float acc[BB];
#pragma unroll
    for (int b = 0; b < BB; b++) acc[b] = 0.f;
#pragma unroll
    for (int o = 0; o < OSEG; o++) {
#pragma unroll
        for (int b = 0; b < BB; b++)
            acc[b] = fmaf(wv[o], ls[b * OSEG + o], acc[b]);
    }
#pragma unroll
    for (int b = 0; b < BB; b++)
        g_qpart[(size_t)oc * BB * HH + b * HH + h] = acc[b];
}

// ---------------------------------------------------------------------
// Kernel 2: reduce OCH q-partials -> g_q (done ONCE, so the 256 fused
// blocks read 4 KB each instead of 256 KB each; removes ~64 MB L2 traffic).
// grid 32 blocks x 64 threads, float4; g_qpart is L2-resident.
// ---------------------------------------------------------------------
__global__ void k_qreduce() {
    const int i4 = blockIdx.x * 64 + threadIdx.x;   // float4 idx in [0, 2048)
    const float4* qp = reinterpret_cast<const float4*>(g_qpart) + i4;
    float4 s = make_float4(0.f, 0.f, 0.f, 0.f);
#pragma unroll 16
    for (int oc = 0; oc < OCH; oc++) {
        float4 p = qp[(size_t)oc * (BB * HH / 4)];
        s.x += p.x; s.y += p.y; s.z += p.z; s.w += p.w;
    }
    reinterpret_cast<float4*>(g_q)[i4] = s;
}

// ---------------------------------------------------------------------
// Kernel 3: fused score + online-softmax + context, single pass over value.
// Block = 256 threads (8 warps), grid (RANGES, BB) = 256 blocks, 2 CTAs/SM.
// One row per warp per iteration, double-buffered prefetch: next row's 8
// float4 loads issue BEFORE current row's softmax math, so the memory pipe
// never drains on the exp/rescale dependency chain. cx-rescale (32 FMA +
// exp) runs only on the warp-uniform rare event m_new > mw.
// Lane l, reg 4j+k maps to h = j*128 + l*4 + k.
// ---------------------------------------------------------------------
__global__ __launch_bounds__(256, 2)
void k_fused(const float* __restrict__ value) {
    __shared__ float4 q_sm[HH / 4];               // 4 KB
    __shared__ float4 red_c[(NW / 2) * (HH / 4)]; // 16 KB
    __shared__ float red_m[NW], red_s[NW];

    const int b = blockIdx.y;
    const int r = blockIdx.x;
    const int tid = threadIdx.x;
    const int w = tid >> 5, l = tid & 31;

    q_sm[tid] = reinterpret_cast<const float4*>(g_q)[b * (HH / 4) + tid];
    __syncthreads();

    float cx[32];
#pragma unroll
    for (int i = 0; i < 32; i++) cx[i] = 0.f;
    float mw = -1e30f, sw = 0.f;

    const float4* vb = reinterpret_cast<const float4*>(value)
                     + ((size_t)b * TT + (size_t)r * TR) * (HH / 4);

    float4 va[2][8];
    {
        const float4* p0 = vb + (size_t)w * (HH / 4) + l;
#pragma unroll
        for (int j = 0; j < 8; j++) va[0][j] = p0[j * 32];
    }

#pragma unroll
    for (int it = 0; it < NITER; it++) {
        const int cur = it & 1, nxt = cur ^ 1;
        if (it + 1 < NITER) {
            const float4* pn = vb + (size_t)((it + 1) * NW + w) * (HH / 4) + l;
#pragma unroll
            for (int j = 0; j < 8; j++) va[nxt][j] = pn[j * 32];
        }

        float d = 0.f;
#pragma unroll
        for (int j = 0; j < 8; j++) {
            float4 q = q_sm[j * 32 + l];
            d = fmaf(va[cur][j].x, q.x, d);
            d = fmaf(va[cur][j].y, q.y, d);
            d = fmaf(va[cur][j].z, q.z, d);
            d = fmaf(va[cur][j].w, q.w, d);
        }
#pragma unroll
        for (int off = 16; off; off >>= 1)
            d += __shfl_xor_sync(0xFFFFFFFFu, d, off);

        if (d > mw) {                         // warp-uniform, rare after warmup
            const float resc = __expf(mw - d);
            mw = d;
            sw *= resc;
#pragma unroll
            for (int i = 0; i < 32; i++) cx[i] *= resc;
        }
        const float ps = __expf(d - mw);
        sw += ps;
#pragma unroll
        for (int j = 0; j < 8; j++) {
            cx[4*j+0] = fmaf(ps, va[cur][j].x, cx[4*j+0]);
            cx[4*j+1] = fmaf(ps, va[cur][j].y, cx[4*j+1]);
            cx[4*j+2] = fmaf(ps, va[cur][j].z, cx[4*j+2]);
            cx[4*j+3] = fmaf(ps, va[cur][j].w, cx[4*j+3]);
        }
    }

    // Cross-warp tree merge of (m, s, c) online-softmax partials.
#pragma unroll
    for (int half = NW / 2; half >= 1; half >>= 1) {
        __syncthreads();
        if (w >= half && w < 2 * half) {
            const int slot = w - half;
#pragma unroll
            for (int j = 0; j < 8; j++)
                red_c[slot * (HH / 4) + j * 32 + l] =
                    make_float4(cx[4*j], cx[4*j+1], cx[4*j+2], cx[4*j+3]);
            if (l == 0) { red_m[slot] = mw; red_s[slot] = sw; }
        }
        __syncthreads();
        if (w < half) {
            const float mo = red_m[w], so = red_s[w];
            const float M  = fmaxf(mw, mo);
            const float ea = __expf(mw - M);
            const float eb = __expf(mo - M);
#pragma unroll
            for (int j = 0; j < 8; j++) {
                float4 o = red_c[w * (HH / 4) + j * 32 + l];
                cx[4*j+0] = cx[4*j+0] * ea + o.x * eb;
                cx[4*j+1] = cx[4*j+1] * ea + o.y * eb;
                cx[4*j+2] = cx[4*j+2] * ea + o.z * eb;
                cx[4*j+3] = cx[4*j+3] * ea + o.w * eb;
            }
            sw = sw * ea + so * eb;
            mw = M;
        }
    }

    if (w == 0) {
        float4* cp = reinterpret_cast<float4*>(g_cpart)
                   + (size_t)(b * RANGES + r) * (HH / 4);
#pragma unroll
        for (int j = 0; j < 8; j++)
            cp[j * 32 + l] = make_float4(cx[4*j], cx[4*j+1], cx[4*j+2], cx[4*j+3]);
        if (l == 0) {
            g_mpart[b * RANGES + r] = mw;
            g_spart[b * RANGES + r] = sw;
        }
    }
}

// ---------------------------------------------------------------------
// Kernel 4: combine the RANGES block-partials -> out [B,1,H].
// grid (BB, 4), block 64; one float4 of h per thread, 32 L2 loads each.
// ---------------------------------------------------------------------
__global__ void k_combine(float* __restrict__ out) {
    const int b = blockIdx.x;
    const int h4 = blockIdx.y * 64 + threadIdx.x;  // float4 index in [0,256)

    float M = -1e30f;
#pragma unroll
    for (int rr = 0; rr < RANGES; rr++)
        M = fmaxf(M, g_mpart[b * RANGES + rr]);

    float D = 0.f;
    float4 acc = make_float4(0.f, 0.f, 0.f, 0.f);
    const float4* cp = reinterpret_cast<const float4*>(g_cpart)
                     + (size_t)b * RANGES * (HH / 4);
#pragma unroll
    for (int rr = 0; rr < RANGES; rr++) {
        const float wgt = __expf(g_mpart[b * RANGES + rr] - M);
        D = fmaf(g_spart[b * RANGES + rr], wgt, D);
        float4 c4 = cp[rr * (HH / 4) + h4];
        acc.x = fmaf(wgt, c4.x, acc.x);
        acc.y = fmaf(wgt, c4.y, acc.y);
        acc.z = fmaf(wgt, c4.z, acc.z);
        acc.w = fmaf(wgt, c4.w, acc.w);
    }
    const float inv = 1.f / D;
    reinterpret_cast<float4*>(out)[b * (HH / 4) + h4] =
        make_float4(acc.x * inv, acc.y * inv, acc.z * inv, acc.w * inv);
}

// ---------------------------------------------------------------------
extern "C" void kernel_launch(void* const* d_in, const int* in_sizes, int n_in,
                              void* d_out, int out_size) {
    const float* value = (const float*)d_in[0];  // [B,T,H]
    const float* last  = (const float*)d_in[1];  // [B,H]
    const float* W     = (const float*)d_in[2];  // [H,H]
    // d_in[3] = bias: constant per-batch shift in scores, cancels in softmax.
    float* out = (float*)d_out;                  // [B,1,H]
    (void)in_sizes; (void)n_in; (void)out_size;

    dim3 gq(HH / 128, OCH);
    k_query_part<<<gq, 128>>>(W, last);

    k_qreduce<<<32, 64>>>();

    dim3 gf(RANGES, BB);
    k_fused<<<gf, 256>>>(value);

    dim3 gc(BB, 4);
    k_combine<<<gc, 64>>>(out);
}

// round 8
// speedup vs baseline: 1.0034x; 1.0034x over previous
#include <cuda_runtime.h>
#include <cstdint>

// Shapes fixed: value [8,4096,1024], last [8,1024], W [1024,1024], b [1024].
#define BB 8
#define TT 4096
#define HH 1024

#define RANGES 32              // T-splits per batch (fused kernel grid.x)
#define TR (TT / RANGES)       // 128 timesteps per block
#define NW 8                   // warps per fused block (256 threads)
#define RPW 2                  // rows per warp per iteration
#define NITER (TR / (NW * RPW))// 8 iterations

#define OCH 128                // o-splits for query partials
#define OSEG (HH / OCH)        // 8

// -------- scratch (__device__ globals; no allocation allowed) --------
__device__ __align__(16) float g_qpart[OCH * BB * HH]; // 4 MB (L2-resident)
__device__ __align__(16) float g_q[BB * HH];           // 32 KB reduced q
__device__ __align__(16) float g_cpart[BB * RANGES * HH]; // 1 MB
__device__ float g_mpart[BB * RANGES];
__device__ float g_spart[BB * RANGES];

// ---------------------------------------------------------------------
// Kernel 1: query partials. qpart[oc,b,h] = sum_{o in chunk oc} W[o,h]*last[b,o]
// grid (HH/128, OCH) = 1024 blocks, block 128. 8 fully-unrolled W loads per
// thread, 8 batches per W element. W (4 MB) streamed exactly once.
// ---------------------------------------------------------------------
__global__ void k_query_part(const float* __restrict__ W,
                             const float* __restrict__ last) {
    __shared__ float ls[BB * OSEG];   // 64 floats
    const int oc = blockIdx.y;
    const int h  = blockIdx.x * 128 + threadIdx.x;

    if (threadIdx.x < BB * OSEG) {
        int b = threadIdx.x / OSEG, o = threadIdx.x % OSEG;
        ls[threadIdx.x] = last[b * HH + oc * OSEG + o];
    }
    __syncthreads();

    float wv[OSEG];
#pragma unroll
    for (int o = 0; o < OSEG; o++)
        wv[o] = W[(size_t)(oc * OSEG + o) * HH + h];

    float acc[BB];
#pragma unroll
    for (int b = 0; b < BB; b++) acc[b] = 0.f;
#pragma unroll
    for (int o = 0; o < OSEG; o++) {
#pragma unroll
        for (int b = 0; b < BB; b++)
            acc[b] = fmaf(wv[o], ls[b * OSEG + o], acc[b]);
    }
#pragma unroll
    for (int b = 0; b < BB; b++)
        g_qpart[(size_t)oc * BB * HH + b * HH + h] = acc[b];
}

// ---------------------------------------------------------------------
// Kernel 2: reduce OCH q-partials -> g_q once (fused blocks then read only
// 4 KB each instead of re-reducing; saves ~64 MB of L2 traffic).
// grid 32 blocks x 64 threads, float4; g_qpart is L2-resident.
// ---------------------------------------------------------------------
__global__ void k_qreduce() {
    const int i4 = blockIdx.x * 64 + threadIdx.x;   // float4 idx in [0, 2048)
    const float4* qp = reinterpret_cast<const float4*>(g_qpart) + i4;
    float4 s = make_float4(0.f, 0.f, 0.f, 0.f);
#pragma unroll 16
    for (int oc = 0; oc < OCH; oc++) {
        float4 p = qp[(size_t)oc * (BB * HH / 4)];
        s.x += p.x; s.y += p.y; s.z += p.z; s.w += p.w;
    }
    reinterpret_cast<float4*>(g_q)[i4] = s;
}

// ---------------------------------------------------------------------
// Kernel 3: fused score + online-softmax + context, single pass over value.
// PROVEN R5 mainloop: 2 rows/warp/iter, unconditional rescale, no double
// buffer (the R7 prefetch variant spilled registers and regressed).
// Block = 256 threads (8 warps), grid (RANGES, BB) = 256 blocks, 2 CTAs/SM.
// Lane l, reg 4j+k maps to h = j*128 + l*4 + k.
// ---------------------------------------------------------------------
__global__ __launch_bounds__(256, 2)
void k_fused(const float* __restrict__ value) {
    __shared__ float4 q_sm[HH / 4];               // 4 KB
    __shared__ float4 red_c[(NW / 2) * (HH / 4)]; // 16 KB
    __shared__ float red_m[NW], red_s[NW];

    const int b = blockIdx.y;
    const int r = blockIdx.x;
    const int tid = threadIdx.x;
    const int w = tid >> 5, l = tid & 31;

    q_sm[tid] = reinterpret_cast<const float4*>(g_q)[b * (HH / 4) + tid];
    __syncthreads();

    float cx[32];
#pragma unroll
    for (int i = 0; i < 32; i++) cx[i] = 0.f;
    float mw = -1e30f, sw = 0.f;

    const float4* vb = reinterpret_cast<const float4*>(value)
                     + ((size_t)b * TT + (size_t)r * TR) * (HH / 4);

    for (int it = 0; it < NITER; it++) {
        const int t0 = it * (NW * RPW) + w * RPW;
        const float4* p0 = vb + (size_t)t0 * (HH / 4) + l;
        const float4* p1 = p0 + (HH / 4);

        float4 v0[8], v1[8];
#pragma unroll
        for (int j = 0; j < 8; j++) v0[j] = p0[j * 32];
#pragma unroll
        for (int j = 0; j < 8; j++) v1[j] = p1[j * 32];

        float d0 = 0.f, d1 = 0.f;
#pragma unroll
        for (int j = 0; j < 8; j++) {
            float4 q = q_sm[j * 32 + l];
            d0 = fmaf(v0[j].x, q.x, d0); d0 = fmaf(v0[j].y, q.y, d0);
            d0 = fmaf(v0[j].z, q.z, d0); d0 = fmaf(v0[j].w, q.w, d0);
            d1 = fmaf(v1[j].x, q.x, d1); d1 = fmaf(v1[j].y, q.y, d1);
            d1 = fmaf(v1[j].z, q.z, d1); d1 = fmaf(v1[j].w, q.w, d1);
        }
#pragma unroll
        for (int off = 16; off; off >>= 1) {
            d0 += __shfl_xor_sync(0xFFFFFFFFu, d0, off);
            d1 += __shfl_xor_sync(0xFFFFFFFFu, d1, off);
        }

        const float m_new = fmaxf(mw, fmaxf(d0, d1));
        const float resc = __expf(mw - m_new);
        const float p0s  = __expf(d0 - m_new);
        const float p1s  = __expf(d1 - m_new);
        mw = m_new;
        sw = fmaf(sw, resc, p0s + p1s);
#pragma unroll
        for (int j = 0; j < 8; j++) {
            float t;
            t = cx[4*j+0] * resc; t = fmaf(p0s, v0[j].x, t); cx[4*j+0] = fmaf(p1s, v1[j].x, t);
            t = cx[4*j+1] * resc; t = fmaf(p0s, v0[j].y, t); cx[4*j+1] = fmaf(p1s, v1[j].y, t);
            t = cx[4*j+2] * resc; t = fmaf(p0s, v0[j].z, t); cx[4*j+2] = fmaf(p1s, v1[j].z, t);
            t = cx[4*j+3] * resc; t = fmaf(p0s, v0[j].w, t); cx[4*j+3] = fmaf(p1s, v1[j].w, t);
        }
    }

    // Cross-warp tree merge of (m, s, c) online-softmax partials.
#pragma unroll
    for (int half = NW / 2; half >= 1; half >>= 1) {
        __syncthreads();
        if (w >= half && w < 2 * half) {
            const int slot = w - half;
#pragma unroll
            for (int j = 0; j < 8; j++)
                red_c[slot * (HH / 4) + j * 32 + l] =
                    make_float4(cx[4*j], cx[4*j+1], cx[4*j+2], cx[4*j+3]);
            if (l == 0) { red_m[slot] = mw; red_s[slot] = sw; }
        }
        __syncthreads();
        if (w < half) {
            const float mo = red_m[w], so = red_s[w];
            const float M  = fmaxf(mw, mo);
            const float ea = __expf(mw - M);
            const float eb = __expf(mo - M);
#pragma unroll
            for (int j = 0; j < 8; j++) {
                float4 o = red_c[w * (HH / 4) + j * 32 + l];
                cx[4*j+0] = cx[4*j+0] * ea + o.x * eb;
                cx[4*j+1] = cx[4*j+1] * ea + o.y * eb;
                cx[4*j+2] = cx[4*j+2] * ea + o.z * eb;
                cx[4*j+3] = cx[4*j+3] * ea + o.w * eb;
            }
            sw = sw * ea + so * eb;
            mw = M;
        }
    }

    if (w == 0) {
        float4* cp = reinterpret_cast<float4*>(g_cpart)
                   + (size_t)(b * RANGES + r) * (HH / 4);
#pragma unroll
        for (int j = 0; j < 8; j++)
            cp[j * 32 + l] = make_float4(cx[4*j], cx[4*j+1], cx[4*j+2], cx[4*j+3]);
        if (l == 0) {
            g_mpart[b * RANGES + r] = mw;
            g_spart[b * RANGES + r] = sw;
        }
    }
}

// ---------------------------------------------------------------------
// Kernel 4: combine the RANGES block-partials -> out [B,1,H].
// grid (BB, 8) = 64 blocks x 256 threads (16K threads vs 2K before).
// Warp 0 computes merge weights (wgt[rr], D) into smem once; threads are
// (h4local = tid&31, range-group = tid>>5), 4 independent float4 loads
// each, 8-way smem tree reduce. Kills the 9 us latency straggler.
// ---------------------------------------------------------------------
__global__ void k_combine(float* __restrict__ out) {
    __shared__ float s_wgt[RANGES];
    __shared__ float s_invD;
    __shared__ float4 s_red[8][32];

    const int b   = blockIdx.x;
    const int tid = threadIdx.x;
    const int h4l = tid & 31;             // 0..31
    const int rg  = tid >> 5;             // 0..7 range-group
    const int h4  = blockIdx.y * 32 + h4l;

    // Warp 0: weights. lane rr handles range rr.
    if (tid < 32) {
        float m = g_mpart[b * RANGES + tid];
        float s = g_spart[b * RANGES + tid];
        float M = m;
#pragma unroll
        for (int off = 16; off; off >>= 1)
            M = fmaxf(M, __shfl_xor_sync(0xFFFFFFFFu, M, off));
        const float wg = __expf(m - M);
        float D = s * wg;
#pragma unroll
        for (int off = 16; off; off >>= 1)
            D += __shfl_xor_sync(0xFFFFFFFFu, D, off);
        s_wgt[tid] = wg;
        if (tid == 0) s_invD = 1.f / D;
    }

    // Issue the 4 independent partial loads before the sync.
    const float4* cp = reinterpret_cast<const float4*>(g_cpart)
                     + (size_t)b * RANGES * (HH / 4) + h4;
    float4 c[4];
#pragma unroll
    for (int k = 0; k < 4; k++)
        c[k] = cp[(size_t)(rg * 4 + k) * (HH / 4)];

    __syncthreads();

    float4 acc = make_float4(0.f, 0.f, 0.f, 0.f);
#pragma unroll
    for (int k = 0; k < 4; k++) {
        const float wg = s_wgt[rg * 4 + k];
        acc.x = fmaf(wg, c[k].x, acc.x);
        acc.y = fmaf(wg, c[k].y, acc.y);
        acc.z = fmaf(wg, c[k].z, acc.z);
        acc.w = fmaf(wg, c[k].w, acc.w);
    }
    s_red[rg][h4l] = acc;
    __syncthreads();

    if (rg == 0) {
        float4 t = s_red[0][h4l];
#pragma unroll
        for (int g = 1; g < 8; g++) {
            float4 o = s_red[g][h4l];
            t.x += o.x; t.y += o.y; t.z += o.z; t.w += o.w;
        }
        const float inv = s_invD;
        reinterpret_cast<float4*>(out)[b * (HH / 4) + h4] =
            make_float4(t.x * inv, t.y * inv, t.z * inv, t.w * inv);
    }
}

// ---------------------------------------------------------------------
extern "C" void kernel_launch(void* const* d_in, const int* in_sizes, int n_in,
                              void* d_out, int out_size) {
    const float* value = (const float*)d_in[0];  // [B,T,H]
    const float* last  = (const float*)d_in[1];  // [B,H]
    const float* W     = (const float*)d_in[2];  // [H,H]
    // d_in[3] = bias: constant per-batch shift in scores, cancels in softmax.
    float* out = (float*)d_out;                  // [B,1,H]
    (void)in_sizes; (void)n_in; (void)out_size;

    dim3 gq(HH / 128, OCH);
    k_query_part<<<gq, 128>>>(W, last);

    k_qreduce<<<32, 64>>>();

    dim3 gf(RANGES, BB);
    k_fused<<<gf, 256>>>(value);

    dim3 gc(BB, 8);
    k_combine<<<gc, 256>>>(out);
}

// round 9
// speedup vs baseline: 1.2810x; 1.2767x over previous
#include <cuda_runtime.h>
#include <cstdint>

// Shapes fixed: value [8,4096,1024], last [8,1024], W [1024,1024], b [1024].
#define BB 8
#define TT 4096
#define HH 1024

#define RANGES 32              // T-splits per batch (fused kernel grid.x)
#define TR (TT / RANGES)       // 128 timesteps per block
#define NW 8                   // warps per fused block (256 threads)
#define RPW 2                  // rows per warp per iteration
#define NITER (TR / (NW * RPW))// 8 iterations

#define OCH 128                // o-splits for query
#define OSEG (HH / OCH)        // 8

// -------- scratch (__device__ globals; no allocation allowed) --------
// g_q: zero at load; re-zeroed by the fused kernel's combine epilogue each
// run, so the atomicAdd accumulation in k_query starts from 0 every replay.
__device__ __align__(16) float g_q[BB * HH];
__device__ __align__(16) float g_cpart[BB * RANGES * HH]; // 1 MB
__device__ float g_mpart[BB * RANGES];
__device__ float g_spart[BB * RANGES];
__device__ int   g_cnt[BB];   // per-batch ticket counters (reset by combiner)

// ---------------------------------------------------------------------
// Kernel 1: q[b,h] += sum_{o in chunk} W[o,h]*last[b,o], accumulated with
// atomicAdd (coalesced REDG, 128 adds/address spread over 8K addresses).
// grid (HH/128, OCH) = 1024 blocks, block 128. 8 fully-unrolled W loads
// per thread; W (4 MB) streamed exactly once. No reduce kernel needed.
// ---------------------------------------------------------------------
__global__ void k_query(const float* __restrict__ W,
                        const float* __restrict__ last) {
    __shared__ float ls[BB * OSEG];   // 64 floats
    const int oc = blockIdx.y;
    const int h  = blockIdx.x * 128 + threadIdx.x;

    if (threadIdx.x < BB * OSEG) {
        int b = threadIdx.x / OSEG, o = threadIdx.x % OSEG;
        ls[threadIdx.x] = last[b * HH + oc * OSEG + o];
    }
    __syncthreads();

    float wv[OSEG];
#pragma unroll
    for (int o = 0; o < OSEG; o++)
        wv[o] = W[(size_t)(oc * OSEG + o) * HH + h];

    float acc[BB];
#pragma unroll
    for (int b = 0; b < BB; b++) acc[b] = 0.f;
#pragma unroll
    for (int o = 0; o < OSEG; o++) {
#pragma unroll
        for (int b = 0; b < BB; b++)
            acc[b] = fmaf(wv[o], ls[b * OSEG + o], acc[b]);
    }
#pragma unroll
    for (int b = 0; b < BB; b++)
        atomicAdd(&g_q[b * HH + h], acc[b]);
}

// ---------------------------------------------------------------------
// Kernel 2: fused score + online-softmax + context (proven R5 mainloop)
// PLUS last-block-per-batch combine epilogue (removes the combine launch).
// Block = 256 threads (8 warps), grid (RANGES, BB) = 256 blocks, 2 CTAs/SM.
// Lane l, reg 4j+k maps to h = j*128 + l*4 + k.
// ---------------------------------------------------------------------
__global__ __launch_bounds__(256, 2)
void k_fused(const float* __restrict__ value, float* __restrict__ out) {
    __shared__ float4 q_sm[HH / 4];               // 4 KB
    __shared__ float4 red_c[(NW / 2) * (HH / 4)]; // 16 KB
    __shared__ float red_m[NW], red_s[NW];
    __shared__ float s_wgt[RANGES];
    __shared__ float s_invD;
    __shared__ int   s_ticket;

    const int b = blockIdx.y;
    const int r = blockIdx.x;
    const int tid = threadIdx.x;
    const int w = tid >> 5, l = tid & 31;

    q_sm[tid] = reinterpret_cast<const float4*>(g_q)[b * (HH / 4) + tid];
    __syncthreads();

    float cx[32];
#pragma unroll
    for (int i = 0; i < 32; i++) cx[i] = 0.f;
    float mw = -1e30f, sw = 0.f;

    const float4* vb = reinterpret_cast<const float4*>(value)
                     + ((size_t)b * TT + (size_t)r * TR) * (HH / 4);

    for (int it = 0; it < NITER; it++) {
        const int t0 = it * (NW * RPW) + w * RPW;
        const float4* p0 = vb + (size_t)t0 * (HH / 4) + l;
        const float4* p1 = p0 + (HH / 4);

        float4 v0[8], v1[8];
#pragma unroll
        for (int j = 0; j < 8; j++) v0[j] = p0[j * 32];
#pragma unroll
        for (int j = 0; j < 8; j++) v1[j] = p1[j * 32];

        float d0 = 0.f, d1 = 0.f;
#pragma unroll
        for (int j = 0; j < 8; j++) {
            float4 q = q_sm[j * 32 + l];
            d0 = fmaf(v0[j].x, q.x, d0); d0 = fmaf(v0[j].y, q.y, d0);
            d0 = fmaf(v0[j].z, q.z, d0); d0 = fmaf(v0[j].w, q.w, d0);
            d1 = fmaf(v1[j].x, q.x, d1); d1 = fmaf(v1[j].y, q.y, d1);
            d1 = fmaf(v1[j].z, q.z, d1); d1 = fmaf(v1[j].w, q.w, d1);
        }
#pragma unroll
        for (int off = 16; off; off >>= 1) {
            d0 += __shfl_xor_sync(0xFFFFFFFFu, d0, off);
            d1 += __shfl_xor_sync(0xFFFFFFFFu, d1, off);
        }

        const float m_new = fmaxf(mw, fmaxf(d0, d1));
        const float resc = __expf(mw - m_new);
        const float p0s  = __expf(d0 - m_new);
        const float p1s  = __expf(d1 - m_new);
        mw = m_new;
        sw = fmaf(sw, resc, p0s + p1s);
#pragma unroll
        for (int j = 0; j < 8; j++) {
            float t;
            t = cx[4*j+0] * resc; t = fmaf(p0s, v0[j].x, t); cx[4*j+0] = fmaf(p1s, v1[j].x, t);
            t = cx[4*j+1] * resc; t = fmaf(p0s, v0[j].y, t); cx[4*j+1] = fmaf(p1s, v1[j].y, t);
            t = cx[4*j+2] * resc; t = fmaf(p0s, v0[j].z, t); cx[4*j+2] = fmaf(p1s, v1[j].z, t);
            t = cx[4*j+3] * resc; t = fmaf(p0s, v0[j].w, t); cx[4*j+3] = fmaf(p1s, v1[j].w, t);
        }
    }

    // Cross-warp tree merge of (m, s, c) online-softmax partials.
#pragma unroll
    for (int half = NW / 2; half >= 1; half >>= 1) {
        __syncthreads();
        if (w >= half && w < 2 * half) {
            const int slot = w - half;
#pragma unroll
            for (int j = 0; j < 8; j++)
                red_c[slot * (HH / 4) + j * 32 + l] =
                    make_float4(cx[4*j], cx[4*j+1], cx[4*j+2], cx[4*j+3]);
            if (l == 0) { red_m[slot] = mw; red_s[slot] = sw; }
        }
        __syncthreads();
        if (w < half) {
            const float mo = red_m[w], so = red_s[w];
            const float M  = fmaxf(mw, mo);
            const float ea = __expf(mw - M);
            const float eb = __expf(mo - M);
#pragma unroll
            for (int j = 0; j < 8; j++) {
                float4 o = red_c[w * (HH / 4) + j * 32 + l];
                cx[4*j+0] = cx[4*j+0] * ea + o.x * eb;
                cx[4*j+1] = cx[4*j+1] * ea + o.y * eb;
                cx[4*j+2] = cx[4*j+2] * ea + o.z * eb;
                cx[4*j+3] = cx[4*j+3] * ea + o.w * eb;
            }
            sw = sw * ea + so * eb;
            mw = M;
        }
    }

    if (w == 0) {
        float4* cp = reinterpret_cast<float4*>(g_cpart)
                   + (size_t)(b * RANGES + r) * (HH / 4);
#pragma unroll
        for (int j = 0; j < 8; j++)
            cp[j * 32 + l] = make_float4(cx[4*j], cx[4*j+1], cx[4*j+2], cx[4*j+3]);
        if (l == 0) {
            g_mpart[b * RANGES + r] = mw;
            g_spart[b * RANGES + r] = sw;
        }
    }
    __syncthreads();
    __threadfence();                 // publish this block's partials

    if (tid == 0) s_ticket = atomicAdd(&g_cnt[b], 1);
    __syncthreads();

    // ---- last block of this batch: combine the 32 partials -> out[b] ----
    if (s_ticket == RANGES - 1) {
        __threadfence();             // acquire others' partials

        if (tid < 32) {              // warp 0: merge weights into smem
            float m = g_mpart[b * RANGES + tid];
            float s = g_spart[b * RANGES + tid];
            float M = m;
#pragma unroll
            for (int off = 16; off; off >>= 1)
                M = fmaxf(M, __shfl_xor_sync(0xFFFFFFFFu, M, off));
            const float wg = __expf(m - M);
            float D = s * wg;
#pragma unroll
            for (int off = 16; off; off >>= 1)
                D += __shfl_xor_sync(0xFFFFFFFFu, D, off);
            s_wgt[tid] = wg;
            if (tid == 0) s_invD = 1.f / D;
        }
        __syncthreads();

        const float4* cp = reinterpret_cast<const float4*>(g_cpart)
                         + (size_t)b * RANGES * (HH / 4) + tid;
        float4 acc = make_float4(0.f, 0.f, 0.f, 0.f);
#pragma unroll
        for (int rr = 0; rr < RANGES; rr++) {
            const float wg = s_wgt[rr];
            float4 c4 = cp[(size_t)rr * (HH / 4)];
            acc.x = fmaf(wg, c4.x, acc.x);
            acc.y = fmaf(wg, c4.y, acc.y);
            acc.z = fmaf(wg, c4.z, acc.z);
            acc.w = fmaf(wg, c4.w, acc.w);
        }
        const float inv = s_invD;
        reinterpret_cast<float4*>(out)[b * (HH / 4) + tid] =
            make_float4(acc.x * inv, acc.y * inv, acc.z * inv, acc.w * inv);

        // Re-arm for the next graph replay: zero q[b], reset the counter.
        reinterpret_cast<float4*>(g_q)[b * (HH / 4) + tid] =
            make_float4(0.f, 0.f, 0.f, 0.f);
        __syncthreads();
        if (tid == 0) {
            __threadfence();
            g_cnt[b] = 0;
        }
    }
}

// ---------------------------------------------------------------------
extern "C" void kernel_launch(void* const* d_in, const int* in_sizes, int n_in,
                              void* d_out, int out_size) {
    const float* value = (const float*)d_in[0];  // [B,T,H]
    const float* last  = (const float*)d_in[1];  // [B,H]
    const float* W     = (const float*)d_in[2];  // [H,H]
    // d_in[3] = bias: constant per-batch shift in scores, cancels in softmax.
    float* out = (float*)d_out;                  // [B,1,H]
    (void)in_sizes; (void)n_in; (void)out_size;

    dim3 gq(HH / 128, OCH);
    k_query<<<gq, 128>>>(W, last);

    dim3 gf(RANGES, BB);
    k_fused<<<gf, 256>>>(value, out);
}